// round 1
// baseline (speedup 1.0000x reference)
#include <cuda_runtime.h>
#include <math.h>

// Problem constants
#define T_TOK 2048
#define H_DIM 1024
#define F_DIM 3584
#define N_EXP 8
#define CAP   2048   // max tokens per expert

typedef unsigned long long ull;

// ---------------- device scratch (no allocations allowed) ----------------
__device__ int   g_count[N_EXP];
__device__ int   g_tok[N_EXP * CAP];        // expert -> ordered token list
__device__ int   g_te[T_TOK * 2];           // per-token top-2 expert ids
__device__ int   g_tslot[T_TOK * 2];        // per-token slot within expert list
__device__ float g_tw[T_TOK * 2];           // per-token softmax weights
__device__ float g_act[(size_t)N_EXP * CAP * F_DIM];   // silu(h)*g, 235 MB
__device__ float g_outp[(size_t)N_EXP * CAP * H_DIM];  // per-pair expert output, 67 MB

// ---------------- f32x2 packed-FMA helpers (Blackwell) ----------------
__device__ __forceinline__ ull pack2(float lo, float hi) {
    ull r; asm("mov.b64 %0, {%1,%2};" : "=l"(r) : "f"(lo), "f"(hi)); return r;
}
__device__ __forceinline__ void unpack2(ull v, float& lo, float& hi) {
    asm("mov.b64 {%0,%1}, %2;" : "=f"(lo), "=f"(hi) : "l"(v));
}
__device__ __forceinline__ ull ffma2(ull a, ull b, ull c) {
    ull d; asm("fma.rn.f32x2 %0, %1, %2, %3;" : "=l"(d) : "l"(a), "l"(b), "l"(c));
    return d;
}

// ---------------- kernel 1: gating (logits + top2 + softmax) ----------------
__global__ void k_gate(const float* __restrict__ x, const float* __restrict__ gw) {
    __shared__ float sgw[H_DIM * N_EXP];   // 32 KB
    for (int i = threadIdx.x; i < H_DIM * N_EXP; i += 256) sgw[i] = gw[i];
    __syncthreads();

    int warp = threadIdx.x >> 5, lane = threadIdx.x & 31;
    int t = blockIdx.x * 8 + warp;
    if (t >= T_TOK) return;

    float acc[N_EXP];
#pragma unroll
    for (int e = 0; e < N_EXP; e++) acc[e] = 0.f;
    const float* xr = x + (size_t)t * H_DIM;
    for (int h = lane; h < H_DIM; h += 32) {
        float xv = xr[h];
#pragma unroll
        for (int e = 0; e < N_EXP; e++) acc[e] = fmaf(xv, sgw[h * N_EXP + e], acc[e]);
    }
#pragma unroll
    for (int e = 0; e < N_EXP; e++) {
#pragma unroll
        for (int o = 16; o > 0; o >>= 1) acc[e] += __shfl_xor_sync(0xffffffffu, acc[e], o);
    }
    if (lane == 0) {
        int e0 = 0; float m0 = acc[0];
#pragma unroll
        for (int e = 1; e < N_EXP; e++) if (acc[e] > m0) { m0 = acc[e]; e0 = e; }
        int e1 = -1; float m1 = -3.4e38f;
#pragma unroll
        for (int e = 0; e < N_EXP; e++) if (e != e0 && acc[e] > m1) { m1 = acc[e]; e1 = e; }
        float w0 = 1.f / (1.f + __expf(m1 - m0));
        g_te[2 * t] = e0;  g_te[2 * t + 1] = e1;
        g_tw[2 * t] = w0;  g_tw[2 * t + 1] = 1.f - w0;
    }
}

// ---------------- kernel 2: deterministic per-expert list build ----------------
__global__ void k_build() {
    int e = threadIdx.x >> 5, lane = threadIdx.x & 31;
    if (e >= N_EXP) return;
    int cnt = 0;
    for (int base = 0; base < T_TOK; base += 32) {
        int t = base + lane;
        int a = g_te[2 * t], b = g_te[2 * t + 1];
        bool f1 = (b == e);
        bool f  = (a == e) || f1;
        unsigned mask = __ballot_sync(0xffffffffu, f);
        int pos = cnt + __popc(mask & ((1u << lane) - 1u));
        if (f) {
            g_tok[e * CAP + pos] = t;
            g_tslot[2 * t + (f1 ? 1 : 0)] = pos;
        }
        cnt += __popc(mask);
    }
    if (lane == 0) g_count[e] = cnt;
}

// ---------------- kernel 3: stage-1 GEMMs (h = X w1^T, g = X w3^T) + SwiGLU ----------------
// grid (F/64, CAP/64, E), block 256.  64x64 tile, K-chunk 16, 4x4 thread tile.
__global__ __launch_bounds__(256) void k_ffn1(const float* __restrict__ x,
                                              const float* __restrict__ w1,
                                              const float* __restrict__ w3) {
    int e = blockIdx.z;
    int count = g_count[e];
    int row0 = blockIdx.y * 64;
    if (row0 >= count) return;
    int fBase = blockIdx.x * 64;

    __shared__ float Xs[16][64];
    __shared__ float W1s[16][64];
    __shared__ float W3s[16][64];
    __shared__ int   stok[64];

    int tid = threadIdx.x;
    if (tid < 64) {
        int r = row0 + tid;
        stok[tid] = (r < count) ? g_tok[e * CAP + r] : -1;
    }
    __syncthreads();

    int ty = tid >> 4, tx = tid & 15;
    int lk = tid & 15, lm = tid >> 4;

    ull acc1[4][2], acc2[4][2];
    ull z = pack2(0.f, 0.f);
#pragma unroll
    for (int i = 0; i < 4; i++) { acc1[i][0] = z; acc1[i][1] = z; acc2[i][0] = z; acc2[i][1] = z; }

    const float* w1p = w1 + (size_t)e * F_DIM * H_DIM + (size_t)fBase * H_DIM;
    const float* w3p = w3 + (size_t)e * F_DIM * H_DIM + (size_t)fBase * H_DIM;

    for (int kt = 0; kt < H_DIM; kt += 16) {
#pragma unroll
        for (int i = 0; i < 4; i++) {
            int m = lm + i * 16;
            int tok = stok[m];
            Xs[lk][m]  = (tok >= 0) ? x[(size_t)tok * H_DIM + kt + lk] : 0.f;
            W1s[lk][m] = w1p[(size_t)m * H_DIM + kt + lk];
            W3s[lk][m] = w3p[(size_t)m * H_DIM + kt + lk];
        }
        __syncthreads();
#pragma unroll
        for (int k = 0; k < 16; k++) {
            float4 av = *reinterpret_cast<const float4*>(&Xs[k][ty * 4]);
            ulonglong2 b1 = *reinterpret_cast<const ulonglong2*>(&W1s[k][tx * 4]);
            ulonglong2 b3 = *reinterpret_cast<const ulonglong2*>(&W3s[k][tx * 4]);
            float a_[4] = {av.x, av.y, av.z, av.w};
#pragma unroll
            for (int i = 0; i < 4; i++) {
                ull a2 = pack2(a_[i], a_[i]);
                acc1[i][0] = ffma2(a2, b1.x, acc1[i][0]);
                acc1[i][1] = ffma2(a2, b1.y, acc1[i][1]);
                acc2[i][0] = ffma2(a2, b3.x, acc2[i][0]);
                acc2[i][1] = ffma2(a2, b3.y, acc2[i][1]);
            }
        }
        __syncthreads();
    }

#pragma unroll
    for (int i = 0; i < 4; i++) {
        int m = ty * 4 + i;
        if (row0 + m < count) {
            float* dst = g_act + ((size_t)(e * CAP + row0 + m)) * F_DIM + fBase + tx * 4;
#pragma unroll
            for (int j = 0; j < 2; j++) {
                float h0, h1, g0, g1;
                unpack2(acc1[i][j], h0, h1);
                unpack2(acc2[i][j], g0, g1);
                dst[2 * j]     = (h0 / (1.f + __expf(-h0))) * g0;
                dst[2 * j + 1] = (h1 / (1.f + __expf(-h1))) * g1;
            }
        }
    }
}

// ---------------- kernel 4: stage-2 GEMM (out_pair = act @ w2^T) ----------------
// grid (H/64, CAP/64, E), block 256.
__global__ __launch_bounds__(256) void k_ffn2(const float* __restrict__ w2) {
    int e = blockIdx.z;
    int count = g_count[e];
    int row0 = blockIdx.y * 64;
    if (row0 >= count) return;
    int hBase = blockIdx.x * 64;

    __shared__ float As[16][64];
    __shared__ float Bs[16][64];

    int tid = threadIdx.x;
    int ty = tid >> 4, tx = tid & 15;
    int lk = tid & 15, lm = tid >> 4;

    ull acc[4][2];
    ull z = pack2(0.f, 0.f);
#pragma unroll
    for (int i = 0; i < 4; i++) { acc[i][0] = z; acc[i][1] = z; }

    const float* ap = g_act + ((size_t)(e * CAP + row0)) * F_DIM;
    const float* bp = w2 + (size_t)e * H_DIM * F_DIM + (size_t)hBase * F_DIM;
    int rmax = count - row0; if (rmax > 64) rmax = 64;

    for (int kt = 0; kt < F_DIM; kt += 16) {
#pragma unroll
        for (int i = 0; i < 4; i++) {
            int m = lm + i * 16;
            As[lk][m] = (m < rmax) ? ap[(size_t)m * F_DIM + kt + lk] : 0.f;
            Bs[lk][m] = bp[(size_t)m * F_DIM + kt + lk];
        }
        __syncthreads();
#pragma unroll
        for (int k = 0; k < 16; k++) {
            float4 av = *reinterpret_cast<const float4*>(&As[k][ty * 4]);
            ulonglong2 b = *reinterpret_cast<const ulonglong2*>(&Bs[k][tx * 4]);
            float a_[4] = {av.x, av.y, av.z, av.w};
#pragma unroll
            for (int i = 0; i < 4; i++) {
                ull a2 = pack2(a_[i], a_[i]);
                acc[i][0] = ffma2(a2, b.x, acc[i][0]);
                acc[i][1] = ffma2(a2, b.y, acc[i][1]);
            }
        }
        __syncthreads();
    }

#pragma unroll
    for (int i = 0; i < 4; i++) {
        int m = ty * 4 + i;
        if (m < rmax) {
            float* dst = g_outp + ((size_t)(e * CAP + row0 + m)) * H_DIM + hBase + tx * 4;
#pragma unroll
            for (int j = 0; j < 2; j++) {
                float v0, v1;
                unpack2(acc[i][j], v0, v1);
                dst[2 * j]     = v0;
                dst[2 * j + 1] = v1;
            }
        }
    }
}

// ---------------- kernel 5: weighted combine (deterministic order) ----------------
__global__ void k_comb(float* __restrict__ out) {
    int t = blockIdx.x;
    int e0 = g_te[2 * t], e1 = g_te[2 * t + 1];
    int s0 = g_tslot[2 * t], s1 = g_tslot[2 * t + 1];
    float w0 = g_tw[2 * t], w1 = g_tw[2 * t + 1];
    const float* p0 = g_outp + ((size_t)(e0 * CAP + s0)) * H_DIM;
    const float* p1 = g_outp + ((size_t)(e1 * CAP + s1)) * H_DIM;
    float* o = out + (size_t)t * H_DIM;
    for (int h = threadIdx.x; h < H_DIM; h += 256)
        o[h] = w0 * p0[h] + w1 * p1[h];
}

// ---------------- launch ----------------
extern "C" void kernel_launch(void* const* d_in, const int* in_sizes, int n_in,
                              void* d_out, int out_size) {
    const float* x  = (const float*)d_in[0];
    const float* gw = (const float*)d_in[1];
    const float* w1 = (const float*)d_in[2];
    const float* w3 = (const float*)d_in[3];
    const float* w2 = (const float*)d_in[4];
    float* out = (float*)d_out;

    k_gate<<<T_TOK / 8, 256>>>(x, gw);
    k_build<<<1, 256>>>();
    k_ffn1<<<dim3(F_DIM / 64, CAP / 64, N_EXP), 256>>>(x, w1, w3);
    k_ffn2<<<dim3(H_DIM / 64, CAP / 64, N_EXP), 256>>>(w2);
    k_comb<<<T_TOK, 256>>>(out);
}

// round 2
// speedup vs baseline: 2.0084x; 2.0084x over previous
#include <cuda_runtime.h>
#include <math.h>

// Problem constants
#define T_TOK 2048
#define H_DIM 1024
#define F_DIM 3584
#define N_EXP 8
#define CAP   2048   // max tokens per expert

typedef unsigned long long ull;

// ---------------- device scratch ----------------
__device__ int   g_count[N_EXP];
__device__ int   g_tok[N_EXP * CAP];
__device__ int   g_te[T_TOK * 2];
__device__ int   g_tslot[T_TOK * 2];
__device__ float g_tw[T_TOK * 2];
__device__ float g_act[(size_t)N_EXP * CAP * F_DIM];
__device__ float g_outp[(size_t)N_EXP * CAP * H_DIM];

// ---------------- f32x2 helpers ----------------
__device__ __forceinline__ ull pack2(float lo, float hi) {
    ull r; asm("mov.b64 %0, {%1,%2};" : "=l"(r) : "f"(lo), "f"(hi)); return r;
}
__device__ __forceinline__ void unpack2(ull v, float& lo, float& hi) {
    asm("mov.b64 {%0,%1}, %2;" : "=f"(lo), "=f"(hi) : "l"(v));
}
__device__ __forceinline__ ull ffma2(ull a, ull b, ull c) {
    ull d; asm("fma.rn.f32x2 %0, %1, %2, %3;" : "=l"(d) : "l"(a), "l"(b), "l"(c));
    return d;
}

// ---------------- kernel 1: gating ----------------
__global__ void k_gate(const float* __restrict__ x, const float* __restrict__ gw) {
    __shared__ float sgw[H_DIM * N_EXP];
    for (int i = threadIdx.x; i < H_DIM * N_EXP; i += 256) sgw[i] = gw[i];
    __syncthreads();

    int warp = threadIdx.x >> 5, lane = threadIdx.x & 31;
    int t = blockIdx.x * 8 + warp;
    if (t >= T_TOK) return;

    float acc[N_EXP];
#pragma unroll
    for (int e = 0; e < N_EXP; e++) acc[e] = 0.f;
    const float* xr = x + (size_t)t * H_DIM;
    for (int h = lane; h < H_DIM; h += 32) {
        float xv = xr[h];
#pragma unroll
        for (int e = 0; e < N_EXP; e++) acc[e] = fmaf(xv, sgw[h * N_EXP + e], acc[e]);
    }
#pragma unroll
    for (int e = 0; e < N_EXP; e++) {
#pragma unroll
        for (int o = 16; o > 0; o >>= 1) acc[e] += __shfl_xor_sync(0xffffffffu, acc[e], o);
    }
    if (lane == 0) {
        int e0 = 0; float m0 = acc[0];
#pragma unroll
        for (int e = 1; e < N_EXP; e++) if (acc[e] > m0) { m0 = acc[e]; e0 = e; }
        int e1 = -1; float m1 = -3.4e38f;
#pragma unroll
        for (int e = 0; e < N_EXP; e++) if (e != e0 && acc[e] > m1) { m1 = acc[e]; e1 = e; }
        float w0 = 1.f / (1.f + __expf(m1 - m0));
        g_te[2 * t] = e0;  g_te[2 * t + 1] = e1;
        g_tw[2 * t] = w0;  g_tw[2 * t + 1] = 1.f - w0;
    }
}

// ---------------- kernel 2: per-expert token lists ----------------
__global__ void k_build() {
    int e = threadIdx.x >> 5, lane = threadIdx.x & 31;
    if (e >= N_EXP) return;
    int cnt = 0;
    for (int base = 0; base < T_TOK; base += 32) {
        int t = base + lane;
        int a = g_te[2 * t], b = g_te[2 * t + 1];
        bool f1 = (b == e);
        bool f  = (a == e) || f1;
        unsigned mask = __ballot_sync(0xffffffffu, f);
        int pos = cnt + __popc(mask & ((1u << lane) - 1u));
        if (f) {
            g_tok[e * CAP + pos] = t;
            g_tslot[2 * t + (f1 ? 1 : 0)] = pos;
        }
        cnt += __popc(mask);
    }
    if (lane == 0) g_count[e] = cnt;
}

// ---------------- kernel 3: stage-1 (h,g) + SwiGLU ----------------
// tile M=128 tokens x N=64 F-cols, K-chunk 16.  block 256, thread tile 8x4 (dual acc).
__global__ __launch_bounds__(256, 2) void k_ffn1(const float* __restrict__ x,
                                                 const float* __restrict__ w1,
                                                 const float* __restrict__ w3) {
    int e = blockIdx.z;
    int count = g_count[e];
    int row0 = blockIdx.y * 128;
    if (row0 >= count) return;
    int fBase = blockIdx.x * 64;

    __shared__ float Xs[16][128];
    __shared__ float W1s[16][64];
    __shared__ float W3s[16][64];
    __shared__ int   stok[128];

    int tid = threadIdx.x;
    if (tid < 128) {
        int r = row0 + tid;
        stok[tid] = (r < count) ? g_tok[e * CAP + r] : -1;
    }
    __syncthreads();

    int ty = tid >> 4, tx = tid & 15;      // compute mapping: 16x16
    // load mapping
    int xr  = tid >> 1,       xko = (tid & 1) * 8;    // Xs: row, k-offset
    int wr  = tid >> 2,       wko = (tid & 3) * 4;    // W tiles

    int xtok = stok[xr];
    const float* xrow = (xtok >= 0) ? (x + (size_t)xtok * H_DIM) : 0;
    const float* w1p = w1 + (size_t)e * F_DIM * H_DIM + ((size_t)fBase + wr) * H_DIM;
    const float* w3p = w3 + (size_t)e * F_DIM * H_DIM + ((size_t)fBase + wr) * H_DIM;

    ull acc1[8][2], acc2[8][2];
    ull z = pack2(0.f, 0.f);
#pragma unroll
    for (int i = 0; i < 8; i++) { acc1[i][0] = z; acc1[i][1] = z; acc2[i][0] = z; acc2[i][1] = z; }

    for (int kt = 0; kt < H_DIM; kt += 16) {
        float4 v0, v1;
        if (xrow) {
            v0 = *reinterpret_cast<const float4*>(xrow + kt + xko);
            v1 = *reinterpret_cast<const float4*>(xrow + kt + xko + 4);
        } else {
            v0 = make_float4(0.f, 0.f, 0.f, 0.f); v1 = v0;
        }
        float4 u1 = *reinterpret_cast<const float4*>(w1p + kt + wko);
        float4 u3 = *reinterpret_cast<const float4*>(w3p + kt + wko);

        Xs[xko + 0][xr] = v0.x; Xs[xko + 1][xr] = v0.y;
        Xs[xko + 2][xr] = v0.z; Xs[xko + 3][xr] = v0.w;
        Xs[xko + 4][xr] = v1.x; Xs[xko + 5][xr] = v1.y;
        Xs[xko + 6][xr] = v1.z; Xs[xko + 7][xr] = v1.w;
        W1s[wko + 0][wr] = u1.x; W1s[wko + 1][wr] = u1.y;
        W1s[wko + 2][wr] = u1.z; W1s[wko + 3][wr] = u1.w;
        W3s[wko + 0][wr] = u3.x; W3s[wko + 1][wr] = u3.y;
        W3s[wko + 2][wr] = u3.z; W3s[wko + 3][wr] = u3.w;
        __syncthreads();

#pragma unroll
        for (int k = 0; k < 16; k++) {
            float4 a0 = *reinterpret_cast<const float4*>(&Xs[k][ty * 8]);
            float4 a1 = *reinterpret_cast<const float4*>(&Xs[k][ty * 8 + 4]);
            ulonglong2 b1 = *reinterpret_cast<const ulonglong2*>(&W1s[k][tx * 4]);
            ulonglong2 b3 = *reinterpret_cast<const ulonglong2*>(&W3s[k][tx * 4]);
            float a_[8] = {a0.x, a0.y, a0.z, a0.w, a1.x, a1.y, a1.z, a1.w};
#pragma unroll
            for (int i = 0; i < 8; i++) {
                ull a2 = pack2(a_[i], a_[i]);
                acc1[i][0] = ffma2(a2, b1.x, acc1[i][0]);
                acc1[i][1] = ffma2(a2, b1.y, acc1[i][1]);
                acc2[i][0] = ffma2(a2, b3.x, acc2[i][0]);
                acc2[i][1] = ffma2(a2, b3.y, acc2[i][1]);
            }
        }
        __syncthreads();
    }

#pragma unroll
    for (int i = 0; i < 8; i++) {
        int m = ty * 8 + i;
        if (row0 + m < count) {
            float* dst = g_act + ((size_t)(e * CAP + row0 + m)) * F_DIM + fBase + tx * 4;
            float r[4];
#pragma unroll
            for (int j = 0; j < 2; j++) {
                float h0, h1, g0, g1;
                unpack2(acc1[i][j], h0, h1);
                unpack2(acc2[i][j], g0, g1);
                r[2 * j]     = (h0 / (1.f + __expf(-h0))) * g0;
                r[2 * j + 1] = (h1 / (1.f + __expf(-h1))) * g1;
            }
            *reinterpret_cast<float4*>(dst) = make_float4(r[0], r[1], r[2], r[3]);
        }
    }
}

// ---------------- kernel 4: stage-2 GEMM ----------------
// tile M=128 tokens x N=128 H-cols, K-chunk 16. block 256, thread tile 8x8.
__global__ __launch_bounds__(256, 2) void k_ffn2(const float* __restrict__ w2) {
    int e = blockIdx.z;
    int count = g_count[e];
    int row0 = blockIdx.y * 128;
    if (row0 >= count) return;
    int hBase = blockIdx.x * 128;

    __shared__ float As[16][128];
    __shared__ float Bs[16][128];

    int tid = threadIdx.x;
    int ty = tid >> 4, tx = tid & 15;
    int lr = tid >> 1, lko = (tid & 1) * 8;

    int rmax = count - row0; if (rmax > 128) rmax = 128;
    const float* ap = (lr < rmax) ? (g_act + ((size_t)(e * CAP + row0 + lr)) * F_DIM) : 0;
    const float* bp = w2 + (size_t)e * H_DIM * F_DIM + ((size_t)hBase + lr) * F_DIM;

    ull acc[8][4];
    ull z = pack2(0.f, 0.f);
#pragma unroll
    for (int i = 0; i < 8; i++) { acc[i][0] = z; acc[i][1] = z; acc[i][2] = z; acc[i][3] = z; }

    for (int kt = 0; kt < F_DIM; kt += 16) {
        float4 a0, a1;
        if (ap) {
            a0 = *reinterpret_cast<const float4*>(ap + kt + lko);
            a1 = *reinterpret_cast<const float4*>(ap + kt + lko + 4);
        } else {
            a0 = make_float4(0.f, 0.f, 0.f, 0.f); a1 = a0;
        }
        float4 b0 = *reinterpret_cast<const float4*>(bp + kt + lko);
        float4 b1 = *reinterpret_cast<const float4*>(bp + kt + lko + 4);

        As[lko + 0][lr] = a0.x; As[lko + 1][lr] = a0.y;
        As[lko + 2][lr] = a0.z; As[lko + 3][lr] = a0.w;
        As[lko + 4][lr] = a1.x; As[lko + 5][lr] = a1.y;
        As[lko + 6][lr] = a1.z; As[lko + 7][lr] = a1.w;
        Bs[lko + 0][lr] = b0.x; Bs[lko + 1][lr] = b0.y;
        Bs[lko + 2][lr] = b0.z; Bs[lko + 3][lr] = b0.w;
        Bs[lko + 4][lr] = b1.x; Bs[lko + 5][lr] = b1.y;
        Bs[lko + 6][lr] = b1.z; Bs[lko + 7][lr] = b1.w;
        __syncthreads();

#pragma unroll
        for (int k = 0; k < 16; k++) {
            float4 a0v = *reinterpret_cast<const float4*>(&As[k][ty * 8]);
            float4 a1v = *reinterpret_cast<const float4*>(&As[k][ty * 8 + 4]);
            ulonglong2 bv0 = *reinterpret_cast<const ulonglong2*>(&Bs[k][tx * 8]);
            ulonglong2 bv1 = *reinterpret_cast<const ulonglong2*>(&Bs[k][tx * 8 + 4]);
            float a_[8] = {a0v.x, a0v.y, a0v.z, a0v.w, a1v.x, a1v.y, a1v.z, a1v.w};
#pragma unroll
            for (int i = 0; i < 8; i++) {
                ull a2 = pack2(a_[i], a_[i]);
                acc[i][0] = ffma2(a2, bv0.x, acc[i][0]);
                acc[i][1] = ffma2(a2, bv0.y, acc[i][1]);
                acc[i][2] = ffma2(a2, bv1.x, acc[i][2]);
                acc[i][3] = ffma2(a2, bv1.y, acc[i][3]);
            }
        }
        __syncthreads();
    }

#pragma unroll
    for (int i = 0; i < 8; i++) {
        int m = ty * 8 + i;
        if (m < rmax) {
            float* dst = g_outp + ((size_t)(e * CAP + row0 + m)) * H_DIM + hBase + tx * 8;
            float r[8];
#pragma unroll
            for (int j = 0; j < 4; j++) unpack2(acc[i][j], r[2 * j], r[2 * j + 1]);
            *reinterpret_cast<float4*>(dst)     = make_float4(r[0], r[1], r[2], r[3]);
            *reinterpret_cast<float4*>(dst + 4) = make_float4(r[4], r[5], r[6], r[7]);
        }
    }
}

// ---------------- kernel 5: weighted combine ----------------
__global__ void k_comb(float* __restrict__ out) {
    int t = blockIdx.x;
    int e0 = g_te[2 * t], e1 = g_te[2 * t + 1];
    int s0 = g_tslot[2 * t], s1 = g_tslot[2 * t + 1];
    float w0 = g_tw[2 * t], w1 = g_tw[2 * t + 1];
    const float4* p0 = (const float4*)(g_outp + ((size_t)(e0 * CAP + s0)) * H_DIM);
    const float4* p1 = (const float4*)(g_outp + ((size_t)(e1 * CAP + s1)) * H_DIM);
    float4* o = (float4*)(out + (size_t)t * H_DIM);
    for (int h = threadIdx.x; h < H_DIM / 4; h += 256) {
        float4 a = p0[h], b = p1[h];
        o[h] = make_float4(w0 * a.x + w1 * b.x, w0 * a.y + w1 * b.y,
                           w0 * a.z + w1 * b.z, w0 * a.w + w1 * b.w);
    }
}

// ---------------- launch ----------------
extern "C" void kernel_launch(void* const* d_in, const int* in_sizes, int n_in,
                              void* d_out, int out_size) {
    const float* x  = (const float*)d_in[0];
    const float* gw = (const float*)d_in[1];
    const float* w1 = (const float*)d_in[2];
    const float* w3 = (const float*)d_in[3];
    const float* w2 = (const float*)d_in[4];
    float* out = (float*)d_out;

    k_gate<<<T_TOK / 8, 256>>>(x, gw);
    k_build<<<1, 256>>>();
    k_ffn1<<<dim3(F_DIM / 64, CAP / 128, N_EXP), 256>>>(x, w1, w3);
    k_ffn2<<<dim3(H_DIM / 128, CAP / 128, N_EXP), 256>>>(w2);
    k_comb<<<T_TOK, 256>>>(out);
}

// round 6
// speedup vs baseline: 6.3719x; 3.1726x over previous
#include <cuda_runtime.h>
#include <cuda_fp16.h>

#define T_TOK 2048
#define H_DIM 1024
#define F_DIM 3584
#define N_EXP 8
#define CAP   2048
#define TOTROW 4096

// ---------------- device scratch ----------------
__device__ int   g_count[N_EXP];
__device__ int   g_off[N_EXP];
__device__ int   g_tok[N_EXP * CAP];
__device__ int   g_te[T_TOK * 2];
__device__ int   g_tslot[T_TOK * 2];
__device__ float g_tw[T_TOK * 2];

__device__ __half g_xh[(size_t)T_TOK * H_DIM];
__device__ __half g_xl[(size_t)T_TOK * H_DIM];   // scratch (unused lo of x)
__device__ __half g_w1h[(size_t)N_EXP * F_DIM * H_DIM];
__device__ __half g_w1l[(size_t)N_EXP * F_DIM * H_DIM];
__device__ __half g_w3h[(size_t)N_EXP * F_DIM * H_DIM];
__device__ __half g_w3l[(size_t)N_EXP * F_DIM * H_DIM];
__device__ __half g_w2h[(size_t)N_EXP * H_DIM * F_DIM];
__device__ __half g_w2l[(size_t)N_EXP * H_DIM * F_DIM];
__device__ __half g_act[(size_t)TOTROW * F_DIM];
__device__ float  g_outp[(size_t)TOTROW * H_DIM];

// ---------------- helpers ----------------
__device__ __forceinline__ unsigned s2u(const void* p) {
    unsigned a;
    asm("{ .reg .u64 t; cvta.to.shared.u64 t, %1; cvt.u32.u64 %0, t; }" : "=r"(a) : "l"(p));
    return a;
}
// 128B-row swizzle: 16B chunk index XOR (row & 7)
__device__ __forceinline__ unsigned swz(int row, int chunk) {
    return (unsigned)(row * 128 + ((chunk ^ (row & 7)) << 4));
}

#define LDSM_X4(r0, r1, r2, r3, a)                                           \
    asm volatile("ldmatrix.sync.aligned.m8n8.x4.shared.b16 {%0,%1,%2,%3}, [%4];" \
                 : "=r"(r0), "=r"(r1), "=r"(r2), "=r"(r3) : "r"(a))

#define MMA16816(d, a, b0, b1)                                               \
    asm volatile("mma.sync.aligned.m16n8k16.row.col.f32.f16.f16.f32 "        \
                 "{%0,%1,%2,%3},{%4,%5,%6,%7},{%8,%9},{%0,%1,%2,%3};"        \
                 : "+f"((d)[0]), "+f"((d)[1]), "+f"((d)[2]), "+f"((d)[3])    \
                 : "r"((a)[0]), "r"((a)[1]), "r"((a)[2]), "r"((a)[3]),       \
                   "r"(b0), "r"(b1))

// ---------------- kernel: fp32 -> fp16 hi/lo split (dst chosen device-side) ----------------
__global__ void k_split(const float* __restrict__ s, int which, size_t n4) {
    __half *h, *l;
    switch (which) {
        case 0: h = g_xh;  l = g_xl;  break;
        case 1: h = g_w1h; l = g_w1l; break;
        case 2: h = g_w3h; l = g_w3l; break;
        default: h = g_w2h; l = g_w2l; break;
    }
    size_t i = (size_t)blockIdx.x * blockDim.x + threadIdx.x;
    size_t stride = (size_t)gridDim.x * blockDim.x;
    for (; i < n4; i += stride) {
        float4 v = ((const float4*)s)[i];
        __half h0 = __float2half_rn(v.x), h1 = __float2half_rn(v.y);
        __half h2 = __float2half_rn(v.z), h3 = __float2half_rn(v.w);
        __half l0 = __float2half_rn(v.x - __half2float(h0));
        __half l1 = __float2half_rn(v.y - __half2float(h1));
        __half l2 = __float2half_rn(v.z - __half2float(h2));
        __half l3 = __float2half_rn(v.w - __half2float(h3));
        ushort4 hv, lv;
        hv.x = __half_as_ushort(h0); hv.y = __half_as_ushort(h1);
        hv.z = __half_as_ushort(h2); hv.w = __half_as_ushort(h3);
        lv.x = __half_as_ushort(l0); lv.y = __half_as_ushort(l1);
        lv.z = __half_as_ushort(l2); lv.w = __half_as_ushort(l3);
        ((ushort4*)h)[i] = hv;
        ((ushort4*)l)[i] = lv;
    }
}

// ---------------- kernel: gating ----------------
__global__ void k_gate(const float* __restrict__ x, const float* __restrict__ gw) {
    __shared__ float sgw[H_DIM * N_EXP];
    for (int i = threadIdx.x; i < H_DIM * N_EXP; i += 256) sgw[i] = gw[i];
    __syncthreads();

    int warp = threadIdx.x >> 5, lane = threadIdx.x & 31;
    int t = blockIdx.x * 8 + warp;
    if (t >= T_TOK) return;

    float acc[N_EXP];
#pragma unroll
    for (int e = 0; e < N_EXP; e++) acc[e] = 0.f;
    const float* xr = x + (size_t)t * H_DIM;
    for (int h = lane; h < H_DIM; h += 32) {
        float xv = xr[h];
#pragma unroll
        for (int e = 0; e < N_EXP; e++) acc[e] = fmaf(xv, sgw[h * N_EXP + e], acc[e]);
    }
#pragma unroll
    for (int e = 0; e < N_EXP; e++) {
#pragma unroll
        for (int o = 16; o > 0; o >>= 1) acc[e] += __shfl_xor_sync(0xffffffffu, acc[e], o);
    }
    if (lane == 0) {
        int e0 = 0; float m0 = acc[0];
#pragma unroll
        for (int e = 1; e < N_EXP; e++) if (acc[e] > m0) { m0 = acc[e]; e0 = e; }
        int e1 = -1; float m1 = -3.4e38f;
#pragma unroll
        for (int e = 0; e < N_EXP; e++) if (e != e0 && acc[e] > m1) { m1 = acc[e]; e1 = e; }
        float w0 = 1.f / (1.f + __expf(m1 - m0));
        g_te[2 * t] = e0;  g_te[2 * t + 1] = e1;
        g_tw[2 * t] = w0;  g_tw[2 * t + 1] = 1.f - w0;
    }
}

// ---------------- kernel: per-expert token lists ----------------
__global__ void k_build() {
    int e = threadIdx.x >> 5, lane = threadIdx.x & 31;
    int cnt = 0;
    for (int base = 0; base < T_TOK; base += 32) {
        int t = base + lane;
        int a = g_te[2 * t], b = g_te[2 * t + 1];
        bool f1 = (b == e);
        bool f  = (a == e) || f1;
        unsigned mask = __ballot_sync(0xffffffffu, f);
        int pos = cnt + __popc(mask & ((1u << lane) - 1u));
        if (f) {
            g_tok[e * CAP + pos] = t;
            g_tslot[2 * t + (f1 ? 1 : 0)] = pos;
        }
        cnt += __popc(mask);
    }
    if (lane == 0) g_count[e] = cnt;
    __syncthreads();
    if (threadIdx.x == 0) {
        int o = 0;
        for (int i = 0; i < N_EXP; i++) { g_off[i] = o; o += g_count[i]; }
    }
}

// ---------------- kernel: stage-1 (h = X w1^T, g = X w3^T) + SwiGLU ----------------
// block tile M=128 tokens x N=64 F-cols (w1 AND w3). 8 warps: 4(m) x 2(n).
// warp tile 32x32. K-chunk 64. smem = 48KB static exactly.
__global__ __launch_bounds__(256, 2) void k_ffn1() {
    __shared__ __align__(1024) char sm[49152];

    int e = blockIdx.z;
    int count = g_count[e];
    int row0 = blockIdx.y * 128;
    if (row0 >= count) return;
    int fBase = blockIdx.x * 64;

    int tid = threadIdx.x, lane = tid & 31, wid = tid >> 5;
    int wm = wid >> 1, wn = wid & 1;
    unsigned sb = s2u(sm);
    const unsigned OA = 0, O1H = 16384, O1L = 24576, O3H = 32768, O3L = 40960;

    // per-thread gather rows are fixed across the K loop: row = (tid>>3) + it*32
    int jc = tid & 7;                 // 16B chunk within 128B row
    int rbase = tid >> 3;             // 0..31
    const __half* aptr[4];
#pragma unroll
    for (int it = 0; it < 4; it++) {
        int row = rbase + it * 32;
        int r = row0 + row;
        int tok = (r < count) ? g_tok[e * CAP + r] : -1;
        aptr[it] = (tok >= 0) ? (g_xh + (size_t)tok * H_DIM + jc * 8) : 0;
    }

    float acc1[2][4][4], acc3[2][4][4];
#pragma unroll
    for (int i = 0; i < 2; i++)
#pragma unroll
        for (int j = 0; j < 4; j++)
#pragma unroll
            for (int q = 0; q < 4; q++) { acc1[i][j][q] = 0.f; acc3[i][j][q] = 0.f; }

    for (int kt = 0; kt < H_DIM; kt += 64) {
#pragma unroll
        for (int it = 0; it < 4; it++) {
            int row = rbase + it * 32;
            uint4 v = make_uint4(0, 0, 0, 0);
            if (aptr[it]) v = *(const uint4*)(aptr[it] + kt);
            *(uint4*)(sm + OA + swz(row, jc)) = v;
        }
#pragma unroll
        for (int it = 0; it < 2; it++) {
            int row = rbase + it * 32;
            size_t go = ((size_t)e * F_DIM + fBase + row) * H_DIM + kt + jc * 8;
            unsigned d = swz(row, jc);
            *(uint4*)(sm + O1H + d) = *(const uint4*)(g_w1h + go);
            *(uint4*)(sm + O1L + d) = *(const uint4*)(g_w1l + go);
            *(uint4*)(sm + O3H + d) = *(const uint4*)(g_w3h + go);
            *(uint4*)(sm + O3L + d) = *(const uint4*)(g_w3l + go);
        }
        __syncthreads();

#pragma unroll
        for (int ks = 0; ks < 4; ks++) {
            unsigned af[2][4];
#pragma unroll
            for (int mt = 0; mt < 2; mt++) {
                int row = wm * 32 + mt * 16 + ((lane >> 3) & 1) * 8 + (lane & 7);
                int ch  = 2 * ks + (lane >> 4);
                LDSM_X4(af[mt][0], af[mt][1], af[mt][2], af[mt][3], sb + OA + swz(row, ch));
            }
            int wrow = wn * 32 + ((lane >> 4) & 1) * 8 + (lane & 7);
            int wch  = 2 * ks + ((lane >> 3) & 1);
#pragma unroll
            for (int ntp = 0; ntp < 4; ntp += 2) {
                unsigned d = swz(wrow + ntp * 8, wch);
                unsigned bh[4], bl[4];
                LDSM_X4(bh[0], bh[1], bh[2], bh[3], sb + O1H + d);
                LDSM_X4(bl[0], bl[1], bl[2], bl[3], sb + O1L + d);
#pragma unroll
                for (int mt = 0; mt < 2; mt++) {
                    MMA16816(acc1[mt][ntp],     af[mt], bh[0], bh[1]);
                    MMA16816(acc1[mt][ntp],     af[mt], bl[0], bl[1]);
                    MMA16816(acc1[mt][ntp + 1], af[mt], bh[2], bh[3]);
                    MMA16816(acc1[mt][ntp + 1], af[mt], bl[2], bl[3]);
                }
                LDSM_X4(bh[0], bh[1], bh[2], bh[3], sb + O3H + d);
                LDSM_X4(bl[0], bl[1], bl[2], bl[3], sb + O3L + d);
#pragma unroll
                for (int mt = 0; mt < 2; mt++) {
                    MMA16816(acc3[mt][ntp],     af[mt], bh[0], bh[1]);
                    MMA16816(acc3[mt][ntp],     af[mt], bl[0], bl[1]);
                    MMA16816(acc3[mt][ntp + 1], af[mt], bh[2], bh[3]);
                    MMA16816(acc3[mt][ntp + 1], af[mt], bl[2], bl[3]);
                }
            }
        }
        __syncthreads();
    }

    // epilogue: SwiGLU -> fp16 activations
    int rb = row0 + wm * 32, cb = fBase + wn * 32;
    size_t obase = (size_t)g_off[e] * F_DIM;
#pragma unroll
    for (int mt = 0; mt < 2; mt++) {
#pragma unroll
        for (int nt = 0; nt < 4; nt++) {
            int r = rb + mt * 16 + (lane >> 2);
            int c = cb + nt * 8 + (lane & 3) * 2;
#pragma unroll
            for (int half = 0; half < 2; half++) {
                int rr = r + half * 8;
                if (rr < count) {
                    float h0 = acc1[mt][nt][half * 2],     g0 = acc3[mt][nt][half * 2];
                    float h1 = acc1[mt][nt][half * 2 + 1], g1 = acc3[mt][nt][half * 2 + 1];
                    float a0 = (h0 / (1.f + __expf(-h0))) * g0;
                    float a1 = (h1 / (1.f + __expf(-h1))) * g1;
                    __half2 v = __floats2half2_rn(a0, a1);
                    *(__half2*)(g_act + obase + (size_t)rr * F_DIM + c) = v;
                }
            }
        }
    }
}

// ---------------- kernel: stage-2 (out = act @ w2^T) ----------------
// block tile M=128 x N=128. 8 warps 4(m) x 2(n), warp tile 32x64. K-chunk 64.
__global__ __launch_bounds__(256, 2) void k_ffn2() {
    __shared__ __align__(1024) char sm[49152];

    int e = blockIdx.z;
    int count = g_count[e];
    int row0 = blockIdx.y * 128;
    if (row0 >= count) return;
    int hBase = blockIdx.x * 128;

    int tid = threadIdx.x, lane = tid & 31, wid = tid >> 5;
    int wm = wid >> 1, wn = wid & 1;
    unsigned sb = s2u(sm);
    const unsigned OA = 0, OBH = 16384, OBL = 32768;

    int rmax = count - row0; if (rmax > 128) rmax = 128;
    size_t rowBase = (size_t)(g_off[e] + row0);
    int jc = tid & 7, rbase = tid >> 3;

    float acc[2][8][4];
#pragma unroll
    for (int i = 0; i < 2; i++)
#pragma unroll
        for (int j = 0; j < 8; j++)
#pragma unroll
            for (int q = 0; q < 4; q++) acc[i][j][q] = 0.f;

    for (int kt = 0; kt < F_DIM; kt += 64) {
#pragma unroll
        for (int it = 0; it < 4; it++) {
            int row = rbase + it * 32;
            uint4 v = make_uint4(0, 0, 0, 0);
            if (row < rmax) v = *(const uint4*)(g_act + (rowBase + row) * F_DIM + kt + jc * 8);
            *(uint4*)(sm + OA + swz(row, jc)) = v;
            size_t go = ((size_t)e * H_DIM + hBase + row) * F_DIM + kt + jc * 8;
            unsigned d = swz(row, jc);
            *(uint4*)(sm + OBH + d) = *(const uint4*)(g_w2h + go);
            *(uint4*)(sm + OBL + d) = *(const uint4*)(g_w2l + go);
        }
        __syncthreads();

#pragma unroll
        for (int ks = 0; ks < 4; ks++) {
            unsigned af[2][4];
#pragma unroll
            for (int mt = 0; mt < 2; mt++) {
                int row = wm * 32 + mt * 16 + ((lane >> 3) & 1) * 8 + (lane & 7);
                int ch  = 2 * ks + (lane >> 4);
                LDSM_X4(af[mt][0], af[mt][1], af[mt][2], af[mt][3], sb + OA + swz(row, ch));
            }
            int wrow = wn * 64 + ((lane >> 4) & 1) * 8 + (lane & 7);
            int wch  = 2 * ks + ((lane >> 3) & 1);
#pragma unroll
            for (int ntp = 0; ntp < 8; ntp += 2) {
                unsigned d = swz(wrow + ntp * 8, wch);
                unsigned bh[4], bl[4];
                LDSM_X4(bh[0], bh[1], bh[2], bh[3], sb + OBH + d);
                LDSM_X4(bl[0], bl[1], bl[2], bl[3], sb + OBL + d);
#pragma unroll
                for (int mt = 0; mt < 2; mt++) {
                    MMA16816(acc[mt][ntp],     af[mt], bh[0], bh[1]);
                    MMA16816(acc[mt][ntp],     af[mt], bl[0], bl[1]);
                    MMA16816(acc[mt][ntp + 1], af[mt], bh[2], bh[3]);
                    MMA16816(acc[mt][ntp + 1], af[mt], bl[2], bl[3]);
                }
            }
        }
        __syncthreads();
    }

    int rb = wm * 32, cb = hBase + wn * 64;
#pragma unroll
    for (int mt = 0; mt < 2; mt++) {
#pragma unroll
        for (int nt = 0; nt < 8; nt++) {
            int r = rb + mt * 16 + (lane >> 2);
            int c = cb + nt * 8 + (lane & 3) * 2;
#pragma unroll
            for (int half = 0; half < 2; half++) {
                int rr = r + half * 8;
                if (rr < rmax) {
                    float2 v = make_float2(acc[mt][nt][half * 2], acc[mt][nt][half * 2 + 1]);
                    *(float2*)(g_outp + (rowBase + rr) * H_DIM + c) = v;
                }
            }
        }
    }
}

// ---------------- kernel: weighted combine ----------------
__global__ void k_comb(float* __restrict__ out) {
    int t = blockIdx.x;
    int e0 = g_te[2 * t], e1 = g_te[2 * t + 1];
    int s0 = g_off[e0] + g_tslot[2 * t], s1 = g_off[e1] + g_tslot[2 * t + 1];
    float w0 = g_tw[2 * t], w1 = g_tw[2 * t + 1];
    const float4* p0 = (const float4*)(g_outp + (size_t)s0 * H_DIM);
    const float4* p1 = (const float4*)(g_outp + (size_t)s1 * H_DIM);
    float4* o = (float4*)(out + (size_t)t * H_DIM);
    for (int h = threadIdx.x; h < H_DIM / 4; h += 256) {
        float4 a = p0[h], b = p1[h];
        o[h] = make_float4(w0 * a.x + w1 * b.x, w0 * a.y + w1 * b.y,
                           w0 * a.z + w1 * b.z, w0 * a.w + w1 * b.w);
    }
}

// ---------------- launch (kernel launches ONLY, no dynamic smem) ----------------
extern "C" void kernel_launch(void* const* d_in, const int* in_sizes, int n_in,
                              void* d_out, int out_size) {
    const float* x  = (const float*)d_in[0];
    const float* gw = (const float*)d_in[1];
    const float* w1 = (const float*)d_in[2];
    const float* w3 = (const float*)d_in[3];
    const float* w2 = (const float*)d_in[4];
    float* out = (float*)d_out;

    k_gate<<<T_TOK / 8, 256>>>(x, gw);
    k_build<<<1, 256>>>();

    size_t nx = (size_t)T_TOK * H_DIM / 4;
    size_t nw = (size_t)N_EXP * F_DIM * H_DIM / 4;
    k_split<<<512, 256>>>(x, 0, nx);
    k_split<<<2048, 256>>>(w1, 1, nw);
    k_split<<<2048, 256>>>(w3, 2, nw);
    k_split<<<2048, 256>>>(w2, 3, nw);

    k_ffn1<<<dim3(F_DIM / 64, CAP / 128, N_EXP), 256>>>();
    k_ffn2<<<dim3(H_DIM / 128, CAP / 128, N_EXP), 256>>>();
    k_comb<<<T_TOK, 256>>>(out);
}

// round 8
// speedup vs baseline: 9.0451x; 1.4195x over previous
#include <cuda_runtime.h>
#include <cuda_fp16.h>

#define T_TOK 2048
#define H_DIM 1024
#define F_DIM 3584
#define N_EXP 8
#define CAP   2048
#define TOTROW 4096

// ---------------- device scratch ----------------
__device__ int   g_count[N_EXP];
__device__ int   g_off[N_EXP];
__device__ int   g_tok[N_EXP * CAP];
__device__ int   g_te[T_TOK * 2];
__device__ int   g_tslot[T_TOK * 2];
__device__ float g_tw[T_TOK * 2];

__device__ __half g_xh[(size_t)T_TOK * H_DIM];
__device__ __half g_w1h[(size_t)N_EXP * F_DIM * H_DIM];
__device__ __half g_w3h[(size_t)N_EXP * F_DIM * H_DIM];
__device__ __half g_w2h[(size_t)N_EXP * H_DIM * F_DIM];
__device__ __half g_act[(size_t)TOTROW * F_DIM];
__device__ float  g_outp[(size_t)TOTROW * H_DIM];

// ---------------- helpers ----------------
__device__ __forceinline__ unsigned s2u(const void* p) {
    unsigned a;
    asm("{ .reg .u64 t; cvta.to.shared.u64 t, %1; cvt.u32.u64 %0, t; }" : "=r"(a) : "l"(p));
    return a;
}
// 128B-row swizzle: 16B chunk index XOR (row & 7)
__device__ __forceinline__ unsigned swz(int row, int chunk) {
    return (unsigned)(row * 128 + ((chunk ^ (row & 7)) << 4));
}

#define LDSM_X4(r0, r1, r2, r3, a)                                           \
    asm volatile("ldmatrix.sync.aligned.m8n8.x4.shared.b16 {%0,%1,%2,%3}, [%4];" \
                 : "=r"(r0), "=r"(r1), "=r"(r2), "=r"(r3) : "r"(a))

#define MMA16816(d, a, b0, b1)                                               \
    asm volatile("mma.sync.aligned.m16n8k16.row.col.f32.f16.f16.f32 "        \
                 "{%0,%1,%2,%3},{%4,%5,%6,%7},{%8,%9},{%0,%1,%2,%3};"        \
                 : "+f"((d)[0]), "+f"((d)[1]), "+f"((d)[2]), "+f"((d)[3])    \
                 : "r"((a)[0]), "r"((a)[1]), "r"((a)[2]), "r"((a)[3]),       \
                   "r"(b0), "r"(b1))

// ---------------- kernel: fp32 -> fp16 convert (dst chosen device-side) ----------------
__global__ void k_cvt(const float* __restrict__ s, int which, size_t n4) {
    __half* h;
    switch (which) {
        case 0: h = g_xh;  break;
        case 1: h = g_w1h; break;
        case 2: h = g_w3h; break;
        default: h = g_w2h; break;
    }
    size_t i = (size_t)blockIdx.x * blockDim.x + threadIdx.x;
    size_t stride = (size_t)gridDim.x * blockDim.x;
    for (; i < n4; i += stride) {
        float4 v = ((const float4*)s)[i];
        ushort4 hv;
        hv.x = __half_as_ushort(__float2half_rn(v.x));
        hv.y = __half_as_ushort(__float2half_rn(v.y));
        hv.z = __half_as_ushort(__float2half_rn(v.z));
        hv.w = __half_as_ushort(__float2half_rn(v.w));
        ((ushort4*)h)[i] = hv;
    }
}

// ---------------- kernel: gating ----------------
__global__ void k_gate(const float* __restrict__ x, const float* __restrict__ gw) {
    __shared__ float sgw[H_DIM * N_EXP];
    for (int i = threadIdx.x; i < H_DIM * N_EXP; i += 256) sgw[i] = gw[i];
    __syncthreads();

    int warp = threadIdx.x >> 5, lane = threadIdx.x & 31;
    int t = blockIdx.x * 8 + warp;
    if (t >= T_TOK) return;

    float acc[N_EXP];
#pragma unroll
    for (int e = 0; e < N_EXP; e++) acc[e] = 0.f;
    const float* xr = x + (size_t)t * H_DIM;
    for (int h = lane; h < H_DIM; h += 32) {
        float xv = xr[h];
#pragma unroll
        for (int e = 0; e < N_EXP; e++) acc[e] = fmaf(xv, sgw[h * N_EXP + e], acc[e]);
    }
#pragma unroll
    for (int e = 0; e < N_EXP; e++) {
#pragma unroll
        for (int o = 16; o > 0; o >>= 1) acc[e] += __shfl_xor_sync(0xffffffffu, acc[e], o);
    }
    if (lane == 0) {
        int e0 = 0; float m0 = acc[0];
#pragma unroll
        for (int e = 1; e < N_EXP; e++) if (acc[e] > m0) { m0 = acc[e]; e0 = e; }
        int e1 = -1; float m1 = -3.4e38f;
#pragma unroll
        for (int e = 0; e < N_EXP; e++) if (e != e0 && acc[e] > m1) { m1 = acc[e]; e1 = e; }
        float w0 = 1.f / (1.f + __expf(m1 - m0));
        g_te[2 * t] = e0;  g_te[2 * t + 1] = e1;
        g_tw[2 * t] = w0;  g_tw[2 * t + 1] = 1.f - w0;
    }
}

// ---------------- kernel: per-expert token lists ----------------
__global__ void k_build() {
    int e = threadIdx.x >> 5, lane = threadIdx.x & 31;
    int cnt = 0;
    for (int base = 0; base < T_TOK; base += 32) {
        int t = base + lane;
        int a = g_te[2 * t], b = g_te[2 * t + 1];
        bool f1 = (b == e);
        bool f  = (a == e) || f1;
        unsigned mask = __ballot_sync(0xffffffffu, f);
        int pos = cnt + __popc(mask & ((1u << lane) - 1u));
        if (f) {
            g_tok[e * CAP + pos] = t;
            g_tslot[2 * t + (f1 ? 1 : 0)] = pos;
        }
        cnt += __popc(mask);
    }
    if (lane == 0) g_count[e] = cnt;
    __syncthreads();
    if (threadIdx.x == 0) {
        int o = 0;
        for (int i = 0; i < N_EXP; i++) { g_off[i] = o; o += g_count[i]; }
    }
}

// ---------------- kernel: stage-1 (h = X w1^T, g = X w3^T) + SwiGLU ----------------
// block tile M=128 tokens x N=64 F-cols (w1 AND w3). 8 warps: 4(m) x 2(n).
// warp tile 32x32. K-chunk 64. smem = 32KB static. (R6 structure, lo-terms removed)
__global__ __launch_bounds__(256, 2) void k_ffn1() {
    __shared__ __align__(1024) char sm[32768];

    int e = blockIdx.z;
    int count = g_count[e];
    int row0 = blockIdx.y * 128;
    if (row0 >= count) return;
    int fBase = blockIdx.x * 64;

    int tid = threadIdx.x, lane = tid & 31, wid = tid >> 5;
    int wm = wid >> 1, wn = wid & 1;
    unsigned sb = s2u(sm);
    const unsigned OA = 0, O1H = 16384, O3H = 24576;

    // per-thread gather rows are fixed across the K loop: row = (tid>>3) + it*32
    int jc = tid & 7;                 // 16B chunk within 128B row
    int rbase = tid >> 3;             // 0..31
    const __half* aptr[4];
#pragma unroll
    for (int it = 0; it < 4; it++) {
        int row = rbase + it * 32;
        int r = row0 + row;
        int tok = (r < count) ? g_tok[e * CAP + r] : -1;
        aptr[it] = (tok >= 0) ? (g_xh + (size_t)tok * H_DIM + jc * 8) : 0;
    }

    float acc1[2][4][4], acc3[2][4][4];
#pragma unroll
    for (int i = 0; i < 2; i++)
#pragma unroll
        for (int j = 0; j < 4; j++)
#pragma unroll
            for (int q = 0; q < 4; q++) { acc1[i][j][q] = 0.f; acc3[i][j][q] = 0.f; }

    for (int kt = 0; kt < H_DIM; kt += 64) {
#pragma unroll
        for (int it = 0; it < 4; it++) {
            int row = rbase + it * 32;
            uint4 v = make_uint4(0, 0, 0, 0);
            if (aptr[it]) v = *(const uint4*)(aptr[it] + kt);
            *(uint4*)(sm + OA + swz(row, jc)) = v;
        }
#pragma unroll
        for (int it = 0; it < 2; it++) {
            int row = rbase + it * 32;
            size_t go = ((size_t)e * F_DIM + fBase + row) * H_DIM + kt + jc * 8;
            unsigned d = swz(row, jc);
            *(uint4*)(sm + O1H + d) = *(const uint4*)(g_w1h + go);
            *(uint4*)(sm + O3H + d) = *(const uint4*)(g_w3h + go);
        }
        __syncthreads();

#pragma unroll
        for (int ks = 0; ks < 4; ks++) {
            unsigned af[2][4];
#pragma unroll
            for (int mt = 0; mt < 2; mt++) {
                int row = wm * 32 + mt * 16 + ((lane >> 3) & 1) * 8 + (lane & 7);
                int ch  = 2 * ks + (lane >> 4);
                LDSM_X4(af[mt][0], af[mt][1], af[mt][2], af[mt][3], sb + OA + swz(row, ch));
            }
            int wrow = wn * 32 + ((lane >> 4) & 1) * 8 + (lane & 7);
            int wch  = 2 * ks + ((lane >> 3) & 1);
#pragma unroll
            for (int ntp = 0; ntp < 4; ntp += 2) {
                unsigned d = swz(wrow + ntp * 8, wch);
                unsigned b1[4], b3[4];
                LDSM_X4(b1[0], b1[1], b1[2], b1[3], sb + O1H + d);
                LDSM_X4(b3[0], b3[1], b3[2], b3[3], sb + O3H + d);
#pragma unroll
                for (int mt = 0; mt < 2; mt++) {
                    MMA16816(acc1[mt][ntp],     af[mt], b1[0], b1[1]);
                    MMA16816(acc1[mt][ntp + 1], af[mt], b1[2], b1[3]);
                    MMA16816(acc3[mt][ntp],     af[mt], b3[0], b3[1]);
                    MMA16816(acc3[mt][ntp + 1], af[mt], b3[2], b3[3]);
                }
            }
        }
        __syncthreads();
    }

    // epilogue: SwiGLU -> fp16 activations
    int rb = row0 + wm * 32, cb = fBase + wn * 32;
    size_t obase = (size_t)g_off[e] * F_DIM;
#pragma unroll
    for (int mt = 0; mt < 2; mt++) {
#pragma unroll
        for (int nt = 0; nt < 4; nt++) {
            int r = rb + mt * 16 + (lane >> 2);
            int c = cb + nt * 8 + (lane & 3) * 2;
#pragma unroll
            for (int half = 0; half < 2; half++) {
                int rr = r + half * 8;
                if (rr < count) {
                    float h0 = acc1[mt][nt][half * 2],     g0 = acc3[mt][nt][half * 2];
                    float h1 = acc1[mt][nt][half * 2 + 1], g1 = acc3[mt][nt][half * 2 + 1];
                    float a0 = (h0 / (1.f + __expf(-h0))) * g0;
                    float a1 = (h1 / (1.f + __expf(-h1))) * g1;
                    __half2 v = __floats2half2_rn(a0, a1);
                    *(__half2*)(g_act + obase + (size_t)rr * F_DIM + c) = v;
                }
            }
        }
    }
}

// ---------------- kernel: stage-2 (out = act @ w2^T) ----------------
// block tile M=128 x N=128. 8 warps 4(m) x 2(n), warp tile 32x64. K-chunk 64.
// smem = 32KB static. (R6 structure, lo-terms removed)
__global__ __launch_bounds__(256, 2) void k_ffn2() {
    __shared__ __align__(1024) char sm[32768];

    int e = blockIdx.z;
    int count = g_count[e];
    int row0 = blockIdx.y * 128;
    if (row0 >= count) return;
    int hBase = blockIdx.x * 128;

    int tid = threadIdx.x, lane = tid & 31, wid = tid >> 5;
    int wm = wid >> 1, wn = wid & 1;
    unsigned sb = s2u(sm);
    const unsigned OA = 0, OBH = 16384;

    int rmax = count - row0; if (rmax > 128) rmax = 128;
    size_t rowBase = (size_t)(g_off[e] + row0);
    int jc = tid & 7, rbase = tid >> 3;

    float acc[2][8][4];
#pragma unroll
    for (int i = 0; i < 2; i++)
#pragma unroll
        for (int j = 0; j < 8; j++)
#pragma unroll
            for (int q = 0; q < 4; q++) acc[i][j][q] = 0.f;

    for (int kt = 0; kt < F_DIM; kt += 64) {
#pragma unroll
        for (int it = 0; it < 4; it++) {
            int row = rbase + it * 32;
            uint4 v = make_uint4(0, 0, 0, 0);
            if (row < rmax) v = *(const uint4*)(g_act + (rowBase + row) * F_DIM + kt + jc * 8);
            *(uint4*)(sm + OA + swz(row, jc)) = v;
            size_t go = ((size_t)e * H_DIM + hBase + row) * F_DIM + kt + jc * 8;
            *(uint4*)(sm + OBH + swz(row, jc)) = *(const uint4*)(g_w2h + go);
        }
        __syncthreads();

#pragma unroll
        for (int ks = 0; ks < 4; ks++) {
            unsigned af[2][4];
#pragma unroll
            for (int mt = 0; mt < 2; mt++) {
                int row = wm * 32 + mt * 16 + ((lane >> 3) & 1) * 8 + (lane & 7);
                int ch  = 2 * ks + (lane >> 4);
                LDSM_X4(af[mt][0], af[mt][1], af[mt][2], af[mt][3], sb + OA + swz(row, ch));
            }
            int wrow = wn * 64 + ((lane >> 4) & 1) * 8 + (lane & 7);
            int wch  = 2 * ks + ((lane >> 3) & 1);
#pragma unroll
            for (int ntp = 0; ntp < 8; ntp += 2) {
                unsigned d = swz(wrow + ntp * 8, wch);
                unsigned bh[4];
                LDSM_X4(bh[0], bh[1], bh[2], bh[3], sb + OBH + d);
#pragma unroll
                for (int mt = 0; mt < 2; mt++) {
                    MMA16816(acc[mt][ntp],     af[mt], bh[0], bh[1]);
                    MMA16816(acc[mt][ntp + 1], af[mt], bh[2], bh[3]);
                }
            }
        }
        __syncthreads();
    }

    int rb = wm * 32, cb = hBase + wn * 64;
#pragma unroll
    for (int mt = 0; mt < 2; mt++) {
#pragma unroll
        for (int nt = 0; nt < 8; nt++) {
            int r = rb + mt * 16 + (lane >> 2);
            int c = cb + nt * 8 + (lane & 3) * 2;
#pragma unroll
            for (int half = 0; half < 2; half++) {
                int rr = r + half * 8;
                if (rr < rmax) {
                    float2 v = make_float2(acc[mt][nt][half * 2], acc[mt][nt][half * 2 + 1]);
                    *(float2*)(g_outp + (rowBase + rr) * H_DIM + c) = v;
                }
            }
        }
    }
}

// ---------------- kernel: weighted combine ----------------
__global__ void k_comb(float* __restrict__ out) {
    int t = blockIdx.x;
    int e0 = g_te[2 * t], e1 = g_te[2 * t + 1];
    int s0 = g_off[e0] + g_tslot[2 * t], s1 = g_off[e1] + g_tslot[2 * t + 1];
    float w0 = g_tw[2 * t], w1 = g_tw[2 * t + 1];
    const float4* p0 = (const float4*)(g_outp + (size_t)s0 * H_DIM);
    const float4* p1 = (const float4*)(g_outp + (size_t)s1 * H_DIM);
    float4* o = (float4*)(out + (size_t)t * H_DIM);
    for (int h = threadIdx.x; h < H_DIM / 4; h += 256) {
        float4 a = p0[h], b = p1[h];
        o[h] = make_float4(w0 * a.x + w1 * b.x, w0 * a.y + w1 * b.y,
                           w0 * a.z + w1 * b.z, w0 * a.w + w1 * b.w);
    }
}

// ---------------- launch (kernel launches ONLY, no dynamic smem) ----------------
extern "C" void kernel_launch(void* const* d_in, const int* in_sizes, int n_in,
                              void* d_out, int out_size) {
    const float* x  = (const float*)d_in[0];
    const float* gw = (const float*)d_in[1];
    const float* w1 = (const float*)d_in[2];
    const float* w3 = (const float*)d_in[3];
    const float* w2 = (const float*)d_in[4];
    float* out = (float*)d_out;

    k_gate<<<T_TOK / 8, 256>>>(x, gw);
    k_build<<<1, 256>>>();

    size_t nx = (size_t)T_TOK * H_DIM / 4;
    size_t nw = (size_t)N_EXP * F_DIM * H_DIM / 4;
    k_cvt<<<512, 256>>>(x, 0, nx);
    k_cvt<<<2048, 256>>>(w1, 1, nw);
    k_cvt<<<2048, 256>>>(w3, 2, nw);
    k_cvt<<<2048, 256>>>(w2, 3, nw);

    k_ffn1<<<dim3(F_DIM / 64, CAP / 128, N_EXP), 256>>>();
    k_ffn2<<<dim3(H_DIM / 128, CAP / 128, N_EXP), 256>>>();
    k_comb<<<T_TOK, 256>>>(out);
}